// round 6
// baseline (speedup 1.0000x reference)
#include <cuda_runtime.h>
#include <cuda_bf16.h>
#include <math.h>
#include <cstdint>

// Problem constants (match reference_code)
#define BB 1024   // batch
#define TT 1024   // time
#define DD 2      // input dim
#define HH 32     // hidden
#define GR 128    // 4*HH gate rows per layer

// Proven simplifications:
//  - hx == 0 for every cell call  -> Wh{l} terms vanish; bx+bh fuse
//  - layer 0 has cx == 0          -> c0 = sig(i)*tanh(g)
//  - only rows n = b*T + (T-1) reach the output

__device__ __forceinline__ float ftanh(float v) {
    float r; asm("tanh.approx.f32 %0, %1;" : "=f"(r) : "f"(v)); return r;
}
__device__ __forceinline__ float fsig(float v) {
    // sigmoid(v) = 0.5*tanh(v/2) + 0.5  (single MUFU on the chain)
    return fmaf(0.5f, ftanh(0.5f * v), 0.5f);
}

// Packed f32x2 helpers (FFMA2 — PTX-only on Blackwell, ptxas won't emit it itself)
__device__ __forceinline__ uint64_t pack2(float lo, float hi) {
    uint64_t r; asm("mov.b64 %0, {%1, %2};" : "=l"(r) : "f"(lo), "f"(hi)); return r;
}
__device__ __forceinline__ void unpack2(uint64_t v, float& lo, float& hi) {
    asm("mov.b64 {%0, %1}, %2;" : "=f"(lo), "=f"(hi) : "l"(v));
}
__device__ __forceinline__ void ffma2(uint64_t& d, uint64_t a, uint64_t b) {
    asm("fma.rn.f32x2 %0, %1, %2, %0;" : "+l"(d) : "l"(a), "l"(b));
}

// Swizzled 16B index: identity row layout, column block c XOR'd with (row & 7).
__device__ __forceinline__ int swz(int q) {
    return (q & ~7) | ((q ^ (q >> 3)) & 7);
}

// One dense LSTM layer (hx=0). sW = swizzled row-major [128 rows x 8 col-blocks]
// of 16B units, viewed as ulonglong2 so each load yields 2 packed f32x2 operands.
// Accumulators stay packed (even-k lane, odd-k lane); folded once at the end.
__device__ __forceinline__ void lstm_dense_layer(
    const ulonglong2* __restrict__ sW, const float* __restrict__ shwarp,
    float bi, float bf, float bg, float bo, int lane, float& h, float& c)
{
    ulonglong2 hv[8];
    #pragma unroll
    for (int j = 0; j < 8; j++)
        hv[j] = *reinterpret_cast<const ulonglong2*>(shwarp + 4 * j);  // broadcast

    uint64_t ai = pack2(bi, 0.0f);
    uint64_t af = pack2(bf, 0.0f);
    uint64_t ag = pack2(bg, 0.0f);
    uint64_t ao = pack2(bo, 0.0f);
    const int lx = lane & 7;

    #pragma unroll
    for (int j = 0; j < 8; j++) {
        const int jc = j ^ lx;                         // swizzled column block
        const ulonglong2 wi = sW[(0 * HH + lane) * 8 + jc];
        const ulonglong2 wf = sW[(1 * HH + lane) * 8 + jc];
        const ulonglong2 wg = sW[(2 * HH + lane) * 8 + jc];
        const ulonglong2 wo = sW[(3 * HH + lane) * 8 + jc];
        const ulonglong2 hj = hv[j];
        ffma2(ai, wi.x, hj.x); ffma2(ai, wi.y, hj.y);
        ffma2(af, wf.x, hj.x); ffma2(af, wf.y, hj.y);
        ffma2(ag, wg.x, hj.x); ffma2(ag, wg.y, hj.y);
        ffma2(ao, wo.x, hj.x); ffma2(ao, wo.y, hj.y);
    }
    float l0, l1, gi, gf, gg, go;
    unpack2(ai, l0, l1); gi = l0 + l1;
    unpack2(af, l0, l1); gf = l0 + l1;
    unpack2(ag, l0, l1); gg = l0 + l1;
    unpack2(ao, l0, l1); go = l0 + l1;

    c = c * fsig(gf) + fsig(gi) * ftanh(gg);
    h = fsig(go) * ftanh(c);
}

__global__ __launch_bounds__(256)
void lstm_collapsed_kernel(
    const float* __restrict__ x,
    const float* __restrict__ Wx0, const float* __restrict__ bx0, const float* __restrict__ bh0,
    const float* __restrict__ Wx1, const float* __restrict__ bx1, const float* __restrict__ bh1,
    const float* __restrict__ Wx2, const float* __restrict__ bx2, const float* __restrict__ bh2,
    const float* __restrict__ Wfc, const float* __restrict__ bfc,
    float* __restrict__ out)
{
    __shared__ ulonglong2 sW1[GR * 8];       // 16 KB, swizzled identity copy
    __shared__ ulonglong2 sW2[GR * 8];       // 16 KB
    __shared__ float      sh[8 * HH];        // per-warp h broadcast slabs

    const int tid  = threadIdx.x;
    const int warp = tid >> 5;
    const int lane = tid & 31;
    const int b = blockIdx.x * 8 + warp;     // one warp per batch elem

    // --- Issue ALL small per-lane gmem loads first; latency hides under staging ---
    const float* xr = x + ((size_t)b * TT + (TT - 1)) * DD;
    const float x0v = xr[0];
    const float x1v = xr[1];

    // layer-0 weights/biases (only i,g,o rows matter; f vanishes with cx=0)
    const float2 w0i = *reinterpret_cast<const float2*>(Wx0 + (0 * HH + lane) * DD);
    const float2 w0g = *reinterpret_cast<const float2*>(Wx0 + (2 * HH + lane) * DD);
    const float2 w0o = *reinterpret_cast<const float2*>(Wx0 + (3 * HH + lane) * DD);
    const float b0i = bx0[0 * HH + lane] + bh0[0 * HH + lane];
    const float b0g = bx0[2 * HH + lane] + bh0[2 * HH + lane];
    const float b0o = bx0[3 * HH + lane] + bh0[3 * HH + lane];

    const float b1i = bx1[0 * HH + lane] + bh1[0 * HH + lane];
    const float b1f = bx1[1 * HH + lane] + bh1[1 * HH + lane];
    const float b1g = bx1[2 * HH + lane] + bh1[2 * HH + lane];
    const float b1o = bx1[3 * HH + lane] + bh1[3 * HH + lane];

    const float b2i = bx2[0 * HH + lane] + bh2[0 * HH + lane];
    const float b2f = bx2[1 * HH + lane] + bh2[1 * HH + lane];
    const float b2g = bx2[2 * HH + lane] + bh2[2 * HH + lane];
    const float b2o = bx2[3 * HH + lane] + bh2[3 * HH + lane];

    const float wfc  = Wfc[lane];
    const float bfcv = bfc[0];

    // --- Stage big matrices: identity copy with XOR swizzle (no transpose) ---
    const ulonglong2* W1v = reinterpret_cast<const ulonglong2*>(Wx1);
    const ulonglong2* W2v = reinterpret_cast<const ulonglong2*>(Wx2);
    #pragma unroll
    for (int it = 0; it < 4; it++) {
        const int q  = tid + it * 256;       // 0..1023
        const int sq = swz(q);
        sW1[sq] = W1v[q];
        sW2[sq] = W2v[q];
    }

    // ---- layer 0 (pure registers, no smem dependency) ----
    const float gi0 = fmaf(w0i.y, x1v, fmaf(w0i.x, x0v, b0i));
    const float gg0 = fmaf(w0g.y, x1v, fmaf(w0g.x, x0v, b0g));
    const float go0 = fmaf(w0o.y, x1v, fmaf(w0o.x, x0v, b0o));
    float c = fsig(gi0) * ftanh(gg0);        // f-gate term vanishes (cx=0)
    float h = fsig(go0) * ftanh(c);

    float* shw = sh + warp * HH;
    shw[lane] = h;                           // publish before block barrier
    __syncthreads();                         // sW1/sW2 (and shw) ready

    // ---- layer 1 ----
    lstm_dense_layer(sW1, shw, b1i, b1f, b1g, b1o, lane, h, c);

    // ---- layer 2 ----
    __syncwarp();
    shw[lane] = h;
    __syncwarp();
    lstm_dense_layer(sW2, shw, b2i, b2f, b2g, b2o, lane, h, c);

    // ---- final FC: out[b] = sum_k h[k]*Wfc[k] + bfc ----
    float p = h * wfc;
    #pragma unroll
    for (int off = 16; off > 0; off >>= 1)
        p += __shfl_down_sync(0xffffffffu, p, off);
    if (lane == 0) out[b] = p + bfcv;
}

extern "C" void kernel_launch(void* const* d_in, const int* in_sizes, int n_in,
                              void* d_out, int out_size)
{
    // metadata order: x, Wx0,bx0,Wh0,bh0, Wx1,bx1,Wh1,bh1, Wx2,bx2,Wh2,bh2, Wfc,bfc
    const float* x   = (const float*)d_in[0];
    const float* Wx0 = (const float*)d_in[1];
    const float* bx0 = (const float*)d_in[2];
    const float* bh0 = (const float*)d_in[4];   // Wh0 (d_in[3]) unused: hx == 0
    const float* Wx1 = (const float*)d_in[5];
    const float* bx1 = (const float*)d_in[6];
    const float* bh1 = (const float*)d_in[8];   // Wh1 unused
    const float* Wx2 = (const float*)d_in[9];
    const float* bx2 = (const float*)d_in[10];
    const float* bh2 = (const float*)d_in[12];  // Wh2 unused
    const float* Wfc = (const float*)d_in[13];
    const float* bfc = (const float*)d_in[14];
    float* out = (float*)d_out;

    const int threads = 256;                 // 8 warps = 8 batch elems / block
    const int blocks  = BB / 8;              // 128 blocks -> ~all SMs get one
    lstm_collapsed_kernel<<<blocks, threads>>>(
        x, Wx0, bx0, bh0, Wx1, bx1, bh1, Wx2, bx2, bh2, Wfc, bfc, out);
}

// round 7
// speedup vs baseline: 1.0323x; 1.0323x over previous
#include <cuda_runtime.h>
#include <cuda_bf16.h>
#include <math.h>
#include <cstdint>

// Problem constants (match reference_code)
#define BB 1024   // batch
#define TT 1024   // time
#define DD 2      // input dim
#define HH 32     // hidden
#define GR 128    // 4*HH gate rows per layer

// Proven simplifications:
//  - hx == 0 for every cell call  -> Wh{l} terms vanish; bx+bh fuse
//  - layer 0 has cx == 0          -> c0 = sig(i)*tanh(g)
//  - only rows n = b*T + (T-1) reach the output

__device__ __forceinline__ float ftanh(float v) {
    float r; asm("tanh.approx.f32 %0, %1;" : "=f"(r) : "f"(v)); return r;
}
__device__ __forceinline__ float fsig(float v) {
    // sigmoid(v) = 0.5*tanh(v/2) + 0.5  (single MUFU on the chain)
    return fmaf(0.5f, ftanh(0.5f * v), 0.5f);
}

// Packed f32x2 helpers (FFMA2 — PTX-only; ptxas won't auto-fuse)
__device__ __forceinline__ uint64_t pack2(float lo, float hi) {
    uint64_t r; asm("mov.b64 %0, {%1, %2};" : "=l"(r) : "f"(lo), "f"(hi)); return r;
}
__device__ __forceinline__ void unpack2(uint64_t v, float& lo, float& hi) {
    asm("mov.b64 {%0, %1}, %2;" : "=f"(lo), "=f"(hi) : "l"(v));
}
__device__ __forceinline__ void ffma2(uint64_t& d, uint64_t a, uint64_t b) {
    asm("fma.rn.f32x2 %0, %1, %2, %0;" : "+l"(d) : "l"(a), "l"(b));
}

// Swizzled 16B index: identity row layout, column block c XOR'd with (row & 7).
__device__ __forceinline__ int swz(int q) {
    return (q & ~7) | ((q ^ (q >> 3)) & 7);
}

// One dense LSTM layer (hx=0). sW = swizzled row-major [128 rows x 8 col-blocks]
// of 16B units viewed as ulonglong2 (2 packed f32x2 operands per load).
__device__ __forceinline__ void lstm_dense_layer(
    const ulonglong2* __restrict__ sW, const float* __restrict__ shwarp,
    float bi, float bf, float bg, float bo, int lane, float& h, float& c)
{
    ulonglong2 hv[8];
    #pragma unroll
    for (int j = 0; j < 8; j++)
        hv[j] = *reinterpret_cast<const ulonglong2*>(shwarp + 4 * j);  // broadcast

    uint64_t ai = pack2(bi, 0.0f);
    uint64_t af = pack2(bf, 0.0f);
    uint64_t ag = pack2(bg, 0.0f);
    uint64_t ao = pack2(bo, 0.0f);
    const int lx = lane & 7;

    #pragma unroll
    for (int j = 0; j < 8; j++) {
        const int jc = j ^ lx;                         // swizzled column block
        const ulonglong2 wi = sW[(0 * HH + lane) * 8 + jc];
        const ulonglong2 wf = sW[(1 * HH + lane) * 8 + jc];
        const ulonglong2 wg = sW[(2 * HH + lane) * 8 + jc];
        const ulonglong2 wo = sW[(3 * HH + lane) * 8 + jc];
        const ulonglong2 hj = hv[j];
        ffma2(ai, wi.x, hj.x); ffma2(ai, wi.y, hj.y);
        ffma2(af, wf.x, hj.x); ffma2(af, wf.y, hj.y);
        ffma2(ag, wg.x, hj.x); ffma2(ag, wg.y, hj.y);
        ffma2(ao, wo.x, hj.x); ffma2(ao, wo.y, hj.y);
    }
    float l0, l1, gi, gf, gg, go;
    unpack2(ai, l0, l1); gi = l0 + l1;
    unpack2(af, l0, l1); gf = l0 + l1;
    unpack2(ag, l0, l1); gg = l0 + l1;
    unpack2(ao, l0, l1); go = l0 + l1;

    c = c * fsig(gf) + fsig(gi) * ftanh(gg);
    h = fsig(go) * ftanh(c);
}

__global__ __launch_bounds__(256, 1)
void lstm_collapsed_kernel(
    const float* __restrict__ x,
    const float* __restrict__ Wx0, const float* __restrict__ bx0, const float* __restrict__ bh0,
    const float* __restrict__ Wx1, const float* __restrict__ bx1, const float* __restrict__ bh1,
    const float* __restrict__ Wx2, const float* __restrict__ bx2, const float* __restrict__ bh2,
    const float* __restrict__ Wfc, const float* __restrict__ bfc,
    float* __restrict__ out)
{
    __shared__ ulonglong2 sW1[GR * 8];       // 16 KB, swizzled identity copy
    __shared__ ulonglong2 sW2[GR * 8];       // 16 KB
    __shared__ float      sh[8 * HH];        // per-warp h broadcast slabs

    const int tid  = threadIdx.x;
    const int warp = tid >> 5;
    const int lane = tid & 31;
    const int b = blockIdx.x * 8 + warp;     // one warp per batch elem

    // --- Issue ALL gmem loads up front; latencies overlap each other ---
    const float* xr = x + ((size_t)b * TT + (TT - 1)) * DD;
    const float x0v = xr[0];
    const float x1v = xr[1];

    // W2 staging loads: issued NOW, held in registers; STS deferred past bar #1
    const ulonglong2* W1v = reinterpret_cast<const ulonglong2*>(Wx1);
    const ulonglong2* W2v = reinterpret_cast<const ulonglong2*>(Wx2);
    ulonglong2 w2r[4];
    #pragma unroll
    for (int it = 0; it < 4; it++)
        w2r[it] = W2v[tid + it * 256];

    // layer-0 weights/biases (only i,g,o rows matter; f vanishes with cx=0)
    const float2 w0i = *reinterpret_cast<const float2*>(Wx0 + (0 * HH + lane) * DD);
    const float2 w0g = *reinterpret_cast<const float2*>(Wx0 + (2 * HH + lane) * DD);
    const float2 w0o = *reinterpret_cast<const float2*>(Wx0 + (3 * HH + lane) * DD);
    const float b0i = bx0[0 * HH + lane] + bh0[0 * HH + lane];
    const float b0g = bx0[2 * HH + lane] + bh0[2 * HH + lane];
    const float b0o = bx0[3 * HH + lane] + bh0[3 * HH + lane];

    const float b1i = bx1[0 * HH + lane] + bh1[0 * HH + lane];
    const float b1f = bx1[1 * HH + lane] + bh1[1 * HH + lane];
    const float b1g = bx1[2 * HH + lane] + bh1[2 * HH + lane];
    const float b1o = bx1[3 * HH + lane] + bh1[3 * HH + lane];

    const float b2i = bx2[0 * HH + lane] + bh2[0 * HH + lane];
    const float b2f = bx2[1 * HH + lane] + bh2[1 * HH + lane];
    const float b2g = bx2[2 * HH + lane] + bh2[2 * HH + lane];
    const float b2o = bx2[3 * HH + lane] + bh2[3 * HH + lane];

    const float wfc  = Wfc[lane];
    const float bfcv = bfc[0];

    // --- Stage W1 only (swizzled identity copy) ---
    #pragma unroll
    for (int it = 0; it < 4; it++) {
        const int q = tid + it * 256;        // 0..1023
        sW1[swz(q)] = W1v[q];
    }

    // ---- layer 0 (pure registers, no smem dependency) ----
    const float gi0 = fmaf(w0i.y, x1v, fmaf(w0i.x, x0v, b0i));
    const float gg0 = fmaf(w0g.y, x1v, fmaf(w0g.x, x0v, b0g));
    const float go0 = fmaf(w0o.y, x1v, fmaf(w0o.x, x0v, b0o));
    float c = fsig(gi0) * ftanh(gg0);        // f-gate term vanishes (cx=0)
    float h = fsig(go0) * ftanh(c);

    float* shw = sh + warp * HH;
    shw[lane] = h;                           // publish before bar #1
    __syncthreads();                         // sW1 + h slabs ready

    // --- W2 STS from registers (issue-only cost, overlaps layer-1 compute) ---
    #pragma unroll
    for (int it = 0; it < 4; it++)
        sW2[swz(tid + it * 256)] = w2r[it];

    // ---- layer 1 ----
    lstm_dense_layer(sW1, shw, b1i, b1f, b1g, b1o, lane, h, c);

    shw[lane] = h;                           // publish layer-1 h
    __syncthreads();                         // sW2 ready + h slabs ready (drains STS)

    // ---- layer 2 ----
    lstm_dense_layer(sW2, shw, b2i, b2f, b2g, b2o, lane, h, c);

    // ---- final FC: out[b] = sum_k h[k]*Wfc[k] + bfc ----
    float p = h * wfc;
    #pragma unroll
    for (int off = 16; off > 0; off >>= 1)
        p += __shfl_down_sync(0xffffffffu, p, off);
    if (lane == 0) out[b] = p + bfcv;
}

extern "C" void kernel_launch(void* const* d_in, const int* in_sizes, int n_in,
                              void* d_out, int out_size)
{
    // metadata order: x, Wx0,bx0,Wh0,bh0, Wx1,bx1,Wh1,bh1, Wx2,bx2,Wh2,bh2, Wfc,bfc
    const float* x   = (const float*)d_in[0];
    const float* Wx0 = (const float*)d_in[1];
    const float* bx0 = (const float*)d_in[2];
    const float* bh0 = (const float*)d_in[4];   // Wh0 (d_in[3]) unused: hx == 0
    const float* Wx1 = (const float*)d_in[5];
    const float* bx1 = (const float*)d_in[6];
    const float* bh1 = (const float*)d_in[8];   // Wh1 unused
    const float* Wx2 = (const float*)d_in[9];
    const float* bx2 = (const float*)d_in[10];
    const float* bh2 = (const float*)d_in[12];  // Wh2 unused
    const float* Wfc = (const float*)d_in[13];
    const float* bfc = (const float*)d_in[14];
    float* out = (float*)d_out;

    const int threads = 256;                 // 8 warps = 8 batch elems / block
    const int blocks  = BB / 8;              // 128 blocks -> ~all SMs get one
    lstm_collapsed_kernel<<<blocks, threads>>>(
        x, Wx0, bx0, bh0, Wx1, bx1, bh1, Wx2, bx2, bh2, Wfc, bfc, out);
}

// round 8
// speedup vs baseline: 1.1689x; 1.1324x over previous
#include <cuda_runtime.h>
#include <cuda_bf16.h>
#include <math.h>
#include <cstdint>

// Problem constants (match reference_code)
#define BB 1024   // batch
#define TT 1024   // time
#define DD 2      // input dim
#define HH 32     // hidden
#define GR 128    // 4*HH gate rows per layer

// Proven simplifications:
//  - hx == 0 for every cell call  -> Wh{l} terms vanish; bx+bh fuse
//  - layer 0 has cx == 0          -> c0 = sig(i)*tanh(g)
//  - only rows n = b*T + (T-1) reach the output

__device__ __forceinline__ float ftanh(float v) {
    float r; asm("tanh.approx.f32 %0, %1;" : "=f"(r) : "f"(v)); return r;
}
__device__ __forceinline__ float fsig(float v) {
    // sigmoid(v) = 0.5*tanh(v/2) + 0.5  (single MUFU on the chain)
    return fmaf(0.5f, ftanh(0.5f * v), 0.5f);
}

// Packed f32x2 helpers (FFMA2 — PTX-only; ptxas won't auto-fuse)
__device__ __forceinline__ uint64_t pack2(float lo, float hi) {
    uint64_t r; asm("mov.b64 %0, {%1, %2};" : "=l"(r) : "f"(lo), "f"(hi)); return r;
}
__device__ __forceinline__ void unpack2(uint64_t v, float& lo, float& hi) {
    asm("mov.b64 {%0, %1}, %2;" : "=f"(lo), "=f"(hi) : "l"(v));
}
__device__ __forceinline__ void ffma2(uint64_t& d, uint64_t a, uint64_t b) {
    asm("fma.rn.f32x2 %0, %1, %2, %0;" : "+l"(d) : "l"(a), "l"(b));
}

// Swizzled 16B index: identity row layout, column block c XOR'd with (row & 7).
__device__ __forceinline__ int swz(int q) {
    return (q & ~7) | ((q ^ (q >> 3)) & 7);
}

// 16-byte async copy L2 -> smem (dst carries the swizzle; 16B requires .cg)
__device__ __forceinline__ void cpasync16(uint32_t dst_smem, const void* src) {
    asm volatile("cp.async.cg.shared.global [%0], [%1], 16;"
                 :: "r"(dst_smem), "l"(src) : "memory");
}
__device__ __forceinline__ uint32_t smem_u32(const void* p) {
    return (uint32_t)__cvta_generic_to_shared(p);
}

// One dense LSTM layer (hx=0). sW = swizzled row-major [128 rows x 8 col-blocks]
// of 16B units viewed as ulonglong2 (2 packed f32x2 operands per load).
__device__ __forceinline__ void lstm_dense_layer(
    const ulonglong2* __restrict__ sW, const float* __restrict__ shwarp,
    float bi, float bf, float bg, float bo, int lane, float& h, float& c)
{
    ulonglong2 hv[8];
    #pragma unroll
    for (int j = 0; j < 8; j++)
        hv[j] = *reinterpret_cast<const ulonglong2*>(shwarp + 4 * j);  // broadcast

    uint64_t ai = pack2(bi, 0.0f);
    uint64_t af = pack2(bf, 0.0f);
    uint64_t ag = pack2(bg, 0.0f);
    uint64_t ao = pack2(bo, 0.0f);
    const int lx = lane & 7;

    #pragma unroll
    for (int j = 0; j < 8; j++) {
        const int jc = j ^ lx;                         // swizzled column block
        const ulonglong2 wi = sW[(0 * HH + lane) * 8 + jc];
        const ulonglong2 wf = sW[(1 * HH + lane) * 8 + jc];
        const ulonglong2 wg = sW[(2 * HH + lane) * 8 + jc];
        const ulonglong2 wo = sW[(3 * HH + lane) * 8 + jc];
        const ulonglong2 hj = hv[j];
        ffma2(ai, wi.x, hj.x); ffma2(ai, wi.y, hj.y);
        ffma2(af, wf.x, hj.x); ffma2(af, wf.y, hj.y);
        ffma2(ag, wg.x, hj.x); ffma2(ag, wg.y, hj.y);
        ffma2(ao, wo.x, hj.x); ffma2(ao, wo.y, hj.y);
    }
    float l0, l1, gi, gf, gg, go;
    unpack2(ai, l0, l1); gi = l0 + l1;
    unpack2(af, l0, l1); gf = l0 + l1;
    unpack2(ag, l0, l1); gg = l0 + l1;
    unpack2(ao, l0, l1); go = l0 + l1;

    c = c * fsig(gf) + fsig(gi) * ftanh(gg);
    h = fsig(go) * ftanh(c);
}

__global__ __launch_bounds__(256, 1)
void lstm_collapsed_kernel(
    const float* __restrict__ x,
    const float* __restrict__ Wx0, const float* __restrict__ bx0, const float* __restrict__ bh0,
    const float* __restrict__ Wx1, const float* __restrict__ bx1, const float* __restrict__ bh1,
    const float* __restrict__ Wx2, const float* __restrict__ bx2, const float* __restrict__ bh2,
    const float* __restrict__ Wfc, const float* __restrict__ bfc,
    float* __restrict__ out)
{
    __shared__ ulonglong2 sW1[GR * 8];       // 16 KB, swizzled identity copy
    __shared__ ulonglong2 sW2[GR * 8];       // 16 KB
    __shared__ float      sh[8 * HH];        // per-warp h broadcast slabs

    const int tid  = threadIdx.x;
    const int warp = tid >> 5;
    const int lane = tid & 31;
    const int b = blockIdx.x * 8 + warp;     // one warp per batch elem

    // --- Stage BOTH matrices via cp.async (L2 -> smem, swizzled dst), no RF trip ---
    {
        const uint32_t s1 = smem_u32(sW1);
        const uint32_t s2 = smem_u32(sW2);
        #pragma unroll
        for (int it = 0; it < 4; it++) {
            const int q  = tid + it * 256;               // 0..1023 (16B units)
            const uint32_t d = (uint32_t)(swz(q) * 16);
            cpasync16(s1 + d, (const char*)Wx1 + q * 16);
            cpasync16(s2 + d, (const char*)Wx2 + q * 16);
        }
        asm volatile("cp.async.commit_group;" ::: "memory");
    }

    // --- Small per-lane gmem loads; latencies overlap the async copies ---
    const float* xr = x + ((size_t)b * TT + (TT - 1)) * DD;
    const float x0v = xr[0];
    const float x1v = xr[1];

    // layer-0 weights/biases (only i,g,o rows matter; f vanishes with cx=0)
    const float2 w0i = *reinterpret_cast<const float2*>(Wx0 + (0 * HH + lane) * DD);
    const float2 w0g = *reinterpret_cast<const float2*>(Wx0 + (2 * HH + lane) * DD);
    const float2 w0o = *reinterpret_cast<const float2*>(Wx0 + (3 * HH + lane) * DD);
    const float b0i = bx0[0 * HH + lane] + bh0[0 * HH + lane];
    const float b0g = bx0[2 * HH + lane] + bh0[2 * HH + lane];
    const float b0o = bx0[3 * HH + lane] + bh0[3 * HH + lane];

    const float b1i = bx1[0 * HH + lane] + bh1[0 * HH + lane];
    const float b1f = bx1[1 * HH + lane] + bh1[1 * HH + lane];
    const float b1g = bx1[2 * HH + lane] + bh1[2 * HH + lane];
    const float b1o = bx1[3 * HH + lane] + bh1[3 * HH + lane];

    const float b2i = bx2[0 * HH + lane] + bh2[0 * HH + lane];
    const float b2f = bx2[1 * HH + lane] + bh2[1 * HH + lane];
    const float b2g = bx2[2 * HH + lane] + bh2[2 * HH + lane];
    const float b2o = bx2[3 * HH + lane] + bh2[3 * HH + lane];

    const float wfc  = Wfc[lane];
    const float bfcv = bfc[0];

    // ---- layer 0 (pure registers, no smem dependency) ----
    const float gi0 = fmaf(w0i.y, x1v, fmaf(w0i.x, x0v, b0i));
    const float gg0 = fmaf(w0g.y, x1v, fmaf(w0g.x, x0v, b0g));
    const float go0 = fmaf(w0o.y, x1v, fmaf(w0o.x, x0v, b0o));
    float c = fsig(gi0) * ftanh(gg0);        // f-gate term vanishes (cx=0)
    float h = fsig(go0) * ftanh(c);

    float* shw = sh + warp * HH;
    shw[lane] = h;                           // publish before the single barrier

    asm volatile("cp.async.wait_group 0;" ::: "memory");
    __syncthreads();                         // sW1 + sW2 + all h slabs ready

    // ---- layer 1 ----
    lstm_dense_layer(sW1, shw, b1i, b1f, b1g, b1o, lane, h, c);

    // ---- layer 2 (warp-local h handoff; weights already resident) ----
    __syncwarp();
    shw[lane] = h;
    __syncwarp();
    lstm_dense_layer(sW2, shw, b2i, b2f, b2g, b2o, lane, h, c);

    // ---- final FC: out[b] = sum_k h[k]*Wfc[k] + bfc ----
    float p = h * wfc;
    #pragma unroll
    for (int off = 16; off > 0; off >>= 1)
        p += __shfl_down_sync(0xffffffffu, p, off);
    if (lane == 0) out[b] = p + bfcv;
}

extern "C" void kernel_launch(void* const* d_in, const int* in_sizes, int n_in,
                              void* d_out, int out_size)
{
    // metadata order: x, Wx0,bx0,Wh0,bh0, Wx1,bx1,Wh1,bh1, Wx2,bx2,Wh2,bh2, Wfc,bfc
    const float* x   = (const float*)d_in[0];
    const float* Wx0 = (const float*)d_in[1];
    const float* bx0 = (const float*)d_in[2];
    const float* bh0 = (const float*)d_in[4];   // Wh0 (d_in[3]) unused: hx == 0
    const float* Wx1 = (const float*)d_in[5];
    const float* bx1 = (const float*)d_in[6];
    const float* bh1 = (const float*)d_in[8];   // Wh1 unused
    const float* Wx2 = (const float*)d_in[9];
    const float* bx2 = (const float*)d_in[10];
    const float* bh2 = (const float*)d_in[12];  // Wh2 unused
    const float* Wfc = (const float*)d_in[13];
    const float* bfc = (const float*)d_in[14];
    float* out = (float*)d_out;

    const int threads = 256;                 // 8 warps = 8 batch elems / block
    const int blocks  = BB / 8;              // 128 blocks -> ~all SMs get one
    lstm_collapsed_kernel<<<blocks, threads>>>(
        x, Wx0, bx0, bh0, Wx1, bx1, bh1, Wx2, bx2, bh2, Wfc, bfc, out);
}